// round 9
// baseline (speedup 1.0000x reference)
#include <cuda_runtime.h>

#define E 64
#define H 8
#define HE 512
#define MAX_TOKENS 16384

typedef unsigned long long ull;

__device__ __forceinline__ ull pack2(float lo, float hi) {
    ull r; asm("mov.b64 %0, {%1, %2};" : "=l"(r) : "f"(lo), "f"(hi)); return r;
}
__device__ __forceinline__ float2 unpack2(ull v) {
    float2 f; asm("mov.b64 {%0, %1}, %2;" : "=f"(f.x), "=f"(f.y) : "l"(v)); return f;
}
__device__ __forceinline__ ull ffma2(ull a, ull b, ull c) {
    ull d; asm("fma.rn.f32x2 %0, %1, %2, %3;" : "=l"(d) : "l"(a), "l"(b), "l"(c)); return d;
}

// scratch (device globals: no cudaMalloc allowed)
__device__ __align__(16) float g_q[MAX_TOKENS * HE];
__device__ __align__(16) float g_k[MAX_TOKENS * HE];
__device__ __align__(16) float g_v[MAX_TOKENS * HE];
__device__ __align__(16) float g_res[MAX_TOKENS * HE];

// ---------------------------------------------------------------------------
// Fused QKV GEMM.  O[m][n] = sum_k x[m][k] * W[n][k] + b[n]
// BM=128, BN=64, K=64 staged once. 256 threads, 3 CTAs/SM.
// Warp covers 8 m-groups x 4 n-groups; A half-interleaved (1 wf / LDS.128).
// grid: (24, tokens/128); widx = blockIdx.x>>3, n-block = blockIdx.x&7.
// ---------------------------------------------------------------------------
__global__ void __launch_bounds__(256, 3)
qkv_gemm(const float* __restrict__ x,
         const float* __restrict__ Wq, const float* __restrict__ bq,
         const float* __restrict__ Wk, const float* __restrict__ bk,
         const float* __restrict__ Wv, const float* __restrict__ bv)
{
    extern __shared__ __align__(16) float smem[];
    float (*As)[2][68] = (float (*)[2][68])smem;               // [64][2][68]
    float (*Bs)[68]    = (float (*)[68])(smem + 64 * 2 * 68);  // [64][68]

    const int t    = threadIdx.x;
    const int lane = t & 31;
    const int w    = t >> 5;
    const int m0   = blockIdx.y * 128;
    const int nblk = blockIdx.x;           // 0..23
    const int widx = nblk >> 3;
    const int n0   = (nblk & 7) * 64;

    const float* W    = (widx == 0) ? Wq : (widx == 1) ? Wk : Wv;
    const float* bias = (widx == 0) ? bq : (widx == 1) ? bk : bv;
    float* O          = (widx == 0) ? g_q : (widx == 1) ? g_k : g_v;

    const int G  = (w & 1) * 8 + (lane >> 2);        // m-group 0..15
    const int my = G * 8;                            // 8 m rows
    const int nx = (w >> 1) * 16 + (lane & 3) * 4;   // 4 n cols

    const int lrow = t >> 1, lseg = t & 1;
    const int sg = lrow >> 3, ssub = (lrow >> 2) & 1, spos = lrow & 3;
    const int brow = t >> 2, bseg = t & 3;

    // stage full K=64 tiles
#pragma unroll
    for (int half = 0; half < 2; ++half) {
        const float4* srcA = (const float4*)(x + (size_t)(m0 + lrow) * E + half * 32 + lseg * 16);
#pragma unroll
        for (int i = 0; i < 4; ++i) {
            float4 va = srcA[i];
            int k = half * 32 + lseg * 16 + i * 4;
            As[k + 0][ssub][sg * 4 + spos] = va.x;
            As[k + 1][ssub][sg * 4 + spos] = va.y;
            As[k + 2][ssub][sg * 4 + spos] = va.z;
            As[k + 3][ssub][sg * 4 + spos] = va.w;
        }
    }
    {
        const float4* srcB = (const float4*)(W + (size_t)(n0 + brow) * E + bseg * 16);
#pragma unroll
        for (int i = 0; i < 4; ++i) {
            float4 vb = srcB[i];
            int k = bseg * 16 + i * 4;
            Bs[k + 0][brow] = vb.x; Bs[k + 1][brow] = vb.y;
            Bs[k + 2][brow] = vb.z; Bs[k + 3][brow] = vb.w;
        }
    }
    __syncthreads();

    ull acc[4][4];
#pragma unroll
    for (int p = 0; p < 4; ++p)
#pragma unroll
        for (int j = 0; j < 4; ++j) acc[p][j] = 0ull;

#pragma unroll 8
    for (int k = 0; k < 64; ++k) {
        ulonglong2 qa0 = *(const ulonglong2*)&As[k][0][G * 4];  // m+0..3
        ulonglong2 qa1 = *(const ulonglong2*)&As[k][1][G * 4];  // m+4..7
        ull a[4] = { qa0.x, qa0.y, qa1.x, qa1.y };
        float4 b = *(const float4*)&Bs[k][nx];
        ull b2[4] = { pack2(b.x, b.x), pack2(b.y, b.y),
                      pack2(b.z, b.z), pack2(b.w, b.w) };
#pragma unroll
        for (int j = 0; j < 4; ++j)
#pragma unroll
            for (int p = 0; p < 4; ++p)
                acc[p][j] = ffma2(a[p], b2[j], acc[p][j]);
    }

    float bvv[4];
#pragma unroll
    for (int j = 0; j < 4; ++j) bvv[j] = bias[n0 + nx + j];
#pragma unroll
    for (int p = 0; p < 4; ++p) {
        float2 c0 = unpack2(acc[p][0]);
        float2 c1 = unpack2(acc[p][1]);
        float2 c2 = unpack2(acc[p][2]);
        float2 c3 = unpack2(acc[p][3]);
        float4 o0 = { c0.x + bvv[0], c1.x + bvv[1], c2.x + bvv[2], c3.x + bvv[3] };
        float4 o1 = { c0.y + bvv[0], c1.y + bvv[1], c2.y + bvv[2], c3.y + bvv[3] };
        *(float4*)(O + (size_t)(m0 + my + 2 * p)     * HE + n0 + nx) = o0;
        *(float4*)(O + (size_t)(m0 + my + 2 * p + 1) * HE + n0 + nx) = o1;
    }
}

// ---------------------------------------------------------------------------
// Output GEMM: out[m][n] = sum_k g_res[m][k] * Wu[n][k] + bu[n]
// BM=128, BN=64, BK=64, 256 threads, warp = 8 m-groups x 4 n-groups,
// A half-interleaved like qkv_gemm.
// ---------------------------------------------------------------------------
__global__ void __launch_bounds__(256, 3)
out_gemm(const float* __restrict__ Wu, const float* __restrict__ bu,
         float* __restrict__ out)
{
    extern __shared__ __align__(16) float smem[];
    float (*As)[2][68] = (float (*)[2][68])smem;               // [64][2][68]
    float (*Bs)[68]    = (float (*)[68])(smem + 64 * 2 * 68);  // [64][68]

    const int t    = threadIdx.x;
    const int lane = t & 31;
    const int w    = t >> 5;
    const int m0   = blockIdx.x * 128;

    const int G  = (w & 1) * 8 + (lane >> 2);        // m-group 0..15
    const int my = G * 8;
    const int nx = (w >> 1) * 16 + (lane & 3) * 4;   // 4 n cols

    ull acc[4][4];
#pragma unroll
    for (int p = 0; p < 4; ++p)
#pragma unroll
        for (int j = 0; j < 4; ++j) acc[p][j] = 0ull;

    const int arow = t >> 1, aseg = t & 1;
    const int sg = arow >> 3, ssub = (arow >> 2) & 1, spos = arow & 3;
    const int brow = t >> 2, bseg = t & 3;

    for (int kc = 0; kc < HE; kc += 64) {
        __syncthreads();
        {   // A tile: 128 rows x 64 k (half-interleaved)
            const float4* src = (const float4*)(g_res + (size_t)(m0 + arow) * HE + kc + aseg * 32);
#pragma unroll
            for (int i = 0; i < 8; ++i) {
                float4 v = src[i];
                int k = aseg * 32 + i * 4;
                As[k + 0][ssub][sg * 4 + spos] = v.x;
                As[k + 1][ssub][sg * 4 + spos] = v.y;
                As[k + 2][ssub][sg * 4 + spos] = v.z;
                As[k + 3][ssub][sg * 4 + spos] = v.w;
            }
        }
        {   // B tile: 64 rows x 64 k
            const float4* src = (const float4*)(Wu + (size_t)brow * HE + kc + bseg * 16);
#pragma unroll
            for (int i = 0; i < 4; ++i) {
                float4 v = src[i];
                int k = bseg * 16 + i * 4;
                Bs[k + 0][brow] = v.x; Bs[k + 1][brow] = v.y;
                Bs[k + 2][brow] = v.z; Bs[k + 3][brow] = v.w;
            }
        }
        __syncthreads();
#pragma unroll 8
        for (int k = 0; k < 64; ++k) {
            ulonglong2 qa0 = *(const ulonglong2*)&As[k][0][G * 4];
            ulonglong2 qa1 = *(const ulonglong2*)&As[k][1][G * 4];
            ull a[4] = { qa0.x, qa0.y, qa1.x, qa1.y };
            float4 b = *(const float4*)&Bs[k][nx];
            ull b2[4] = { pack2(b.x, b.x), pack2(b.y, b.y),
                          pack2(b.z, b.z), pack2(b.w, b.w) };
#pragma unroll
            for (int j = 0; j < 4; ++j)
#pragma unroll
                for (int p = 0; p < 4; ++p)
                    acc[p][j] = ffma2(a[p], b2[j], acc[p][j]);
        }
    }

    float bvv[4];
#pragma unroll
    for (int j = 0; j < 4; ++j) bvv[j] = bu[nx + j];
#pragma unroll
    for (int p = 0; p < 4; ++p) {
        float2 c0 = unpack2(acc[p][0]);
        float2 c1 = unpack2(acc[p][1]);
        float2 c2 = unpack2(acc[p][2]);
        float2 c3 = unpack2(acc[p][3]);
        float4 o0 = { c0.x + bvv[0], c1.x + bvv[1], c2.x + bvv[2], c3.x + bvv[3] };
        float4 o1 = { c0.y + bvv[0], c1.y + bvv[1], c2.y + bvv[2], c3.y + bvv[3] };
        *(float4*)(out + (size_t)(m0 + my + 2 * p)     * E + nx) = o0;
        *(float4*)(out + (size_t)(m0 + my + 2 * p + 1) * E + nx) = o1;
    }
}

// ---------------------------------------------------------------------------
// Attention + alpha-entmax + value mix.  (unchanged — protect)
// ---------------------------------------------------------------------------
__global__ void __launch_bounds__(256, 3)
attn_kernel(const float* __restrict__ alpha_p)
{
    // [tl][h][g][8]: floats {cols 4g..4g+3, cols 32+4g..32+4g+3}
    __shared__ __align__(16) float ksw[2][8][8][8];
    __shared__ __align__(16) float vsw[2][8][8][8];

    const int t    = threadIdx.x;
    const int tl   = t >> 7;        // token within CTA
    const int rr   = (t >> 1) & 63; // score row
    const int half = t & 1;         // which 32 columns
    const int base = blockIdx.x * 2;
    const size_t token = (size_t)(base + tl);

    // cooperative load with half-interleaving
    {
        const float4 vk = ((const float4*)(g_k + (size_t)base * HE))[t];
        const float4 vv = ((const float4*)(g_v + (size_t)base * HE))[t];
        const int th = t >> 4;      // tl*8 + h
        const int c  = t & 15;      // float4 within the 64-wide head row
        const int g  = c & 7;
        const int hh = c >> 3;      // which half this float4 belongs to
        float* kd = &ksw[0][0][0][0] + th * 64 + g * 8 + hh * 4;
        float* vd = &vsw[0][0][0][0] + th * 64 + g * 8 + hh * 4;
        *(float4*)kd = vk;
        *(float4*)vd = vv;
    }

    const float alpha = *alpha_p;
    const float am1 = alpha - 1.0f;
    const float inv = 1.0f / am1;
    const float qscale = am1 * 0.125f;   // fold am1 * (1/sqrt(64)) into q

    float qr[H];
#pragma unroll
    for (int h = 0; h < H; ++h)
        qr[h] = g_q[token * HE + h * 64 + rr] * qscale;

    __syncthreads();

    // packed score accumulation: s2[2g+d] holds cols (half*32+4g+2d, +1)
    ull s2[16];
#pragma unroll
    for (int u = 0; u < 16; ++u) s2[u] = 0ull;
#pragma unroll
    for (int h = 0; h < H; ++h) {
        const ull qh2 = pack2(qr[h], qr[h]);
        const ulonglong2* bp = (const ulonglong2*)&ksw[tl][h][0][0];
#pragma unroll
        for (int g = 0; g < 8; ++g) {
            ulonglong2 kk = bp[2 * g + half];
            s2[2 * g]     = ffma2(qh2, kk.x, s2[2 * g]);
            s2[2 * g + 1] = ffma2(qh2, kk.y, s2[2 * g + 1]);
        }
    }
    float s[32];
#pragma unroll
    for (int u = 0; u < 16; ++u) {
        float2 f = unpack2(s2[u]);
        s[2 * u] = f.x; s[2 * u + 1] = f.y;
    }

    float mx = s[0];
#pragma unroll
    for (int j = 1; j < 32; ++j) mx = fmaxf(mx, s[j]);
    mx = fmaxf(mx, __shfl_xor_sync(0xffffffffu, mx, 1));

    if (fabsf(inv - 2.0f) < 1e-4f) {
        // alpha = 1.5: p(z) = relu(z)^2. Newton from below + exact quadratic.
        float tau = mx - 1.0f;
        const float tau_hi = mx - 0.125f;
#pragma unroll 1
        for (int it = 0; it < 4; ++it) {
            float S1 = 0.f, S2 = 0.f;
#pragma unroll
            for (int j = 0; j < 32; ++j) {
                float z = fmaxf(s[j] - tau, 0.0f);
                S1 += z; S2 = fmaf(z, z, S2);
            }
            S1 += __shfl_xor_sync(0xffffffffu, S1, 1);
            S2 += __shfl_xor_sync(0xffffffffu, S2, 1);
            tau = fminf(tau + __fdividef(S2 - 1.0f, 2.0f * S1), tau_hi);
        }
        // exact solve: cnt*tau^2 - 2*S1*tau + (S2-1) = 0 on active set
        float s1 = 0.f, sq = 0.f, cnt = 0.f;
#pragma unroll
        for (int j = 0; j < 32; ++j) {
            float z = s[j] - tau;
            float m = fmaxf(z, 0.0f);
            s1 += m; sq = fmaf(m, m, sq);
            cnt += (z > 0.0f) ? 1.0f : 0.0f;
        }
        s1  += __shfl_xor_sync(0xffffffffu, s1, 1);
        sq  += __shfl_xor_sync(0xffffffffu, sq, 1);
        cnt += __shfl_xor_sync(0xffffffffu, cnt, 1);
        float S1 = fmaf(tau, cnt, s1);
        float S2 = sq + 2.0f * tau * s1 + tau * tau * cnt;
        float disc = fmaxf(fmaf(-cnt, S2 - 1.0f, S1 * S1), 0.0f);
        tau = __fdividef(S1 - sqrtf(disc), cnt);

        float sum = 0.f;
#pragma unroll
        for (int j = 0; j < 32; ++j) {
            float m = fmaxf(s[j] - tau, 0.0f);
            s[j] = m * m;
            sum += s[j];
        }
        sum += __shfl_xor_sync(0xffffffffu, sum, 1);
        float rn = __fdividef(1.0f, sum);
#pragma unroll
        for (int j = 0; j < 32; ++j) s[j] *= rn;
    } else {
        // generic alpha: faithful 50-iter bisection with pair reductions
        float tau_lo = mx - 1.0f;
        float dm = (mx - __powf(1.0f / 64.0f, am1)) - tau_lo;
        float part = 0.f;
#pragma unroll
        for (int j = 0; j < 32; ++j) {
            float z = s[j] - tau_lo;
            if (z > 0.0f) part += __powf(fmaxf(z, 1e-30f), inv);
        }
        part += __shfl_xor_sync(0xffffffffu, part, 1);
        const float f_lo = part - 1.0f;
        float tau_m = tau_lo;
#pragma unroll 1
        for (int it = 0; it < 50; ++it) {
            dm *= 0.5f;
            tau_m = tau_lo + dm;
            float pm = 0.f;
#pragma unroll
            for (int j = 0; j < 32; ++j) {
                float z = s[j] - tau_m;
                if (z > 0.0f) pm += __powf(fmaxf(z, 1e-30f), inv);
            }
            pm += __shfl_xor_sync(0xffffffffu, pm, 1);
            if ((pm - 1.0f) * f_lo >= 0.0f) tau_lo = tau_m;
        }
        float sum = 0.f;
#pragma unroll
        for (int j = 0; j < 32; ++j) {
            float z = s[j] - tau_m;
            s[j] = (z > 0.0f) ? __powf(fmaxf(z, 1e-30f), inv) : 0.0f;
            sum += s[j];
        }
        sum += __shfl_xor_sync(0xffffffffu, sum, 1);
        float rn = __fdividef(1.0f, sum);
#pragma unroll
        for (int j = 0; j < 32; ++j) s[j] *= rn;
    }

    // value mix: res[h][rr] = sum_j att[rr][j] * v[h][j]
    ull att2[16];
#pragma unroll
    for (int u = 0; u < 16; ++u) att2[u] = pack2(s[2 * u], s[2 * u + 1]);
#pragma unroll
    for (int h = 0; h < H; ++h) {
        ull racc = 0ull;
        const ulonglong2* bp = (const ulonglong2*)&vsw[tl][h][0][0];
#pragma unroll
        for (int g = 0; g < 8; ++g) {
            ulonglong2 vv = bp[2 * g + half];
            racc = ffma2(att2[2 * g],     vv.x, racc);
            racc = ffma2(att2[2 * g + 1], vv.y, racc);
        }
        float2 f = unpack2(racc);
        float rh = f.x + f.y;
        rh += __shfl_xor_sync(0xffffffffu, rh, 1);
        if (half == (h & 1))
            g_res[token * HE + h * 64 + rr] = rh;
    }
}

// ---------------------------------------------------------------------------
extern "C" void kernel_launch(void* const* d_in, const int* in_sizes, int n_in,
                              void* d_out, int out_size)
{
    const float* x     = (const float*)d_in[0];
    const float* alpha = (const float*)d_in[1];
    const float* Wk    = (const float*)d_in[2];
    const float* bk    = (const float*)d_in[3];
    const float* Wq    = (const float*)d_in[4];
    const float* bq    = (const float*)d_in[5];
    const float* Wv    = (const float*)d_in[6];
    const float* bv    = (const float*)d_in[7];
    const float* Wu    = (const float*)d_in[8];
    const float* bu    = (const float*)d_in[9];

    const int tokens = in_sizes[0] / E;   // 16384

    const int gem_smem = (64 * 2 * 68 + 64 * 68) * sizeof(float);   // 52224
    static int attr_done = 0;
    if (!attr_done) {
        cudaFuncSetAttribute(qkv_gemm, cudaFuncAttributeMaxDynamicSharedMemorySize, gem_smem);
        cudaFuncSetAttribute(out_gemm, cudaFuncAttributeMaxDynamicSharedMemorySize, gem_smem);
        attr_done = 1;
    }

    qkv_gemm<<<dim3(24, tokens / 128), 256, gem_smem>>>(x, Wq, bq, Wk, bk, Wv, bv);
    attn_kernel<<<tokens / 2, 256>>>(alpha);
    out_gemm<<<tokens / 128, 256, gem_smem>>>(Wu, bu, (float*)d_out);
}

// round 10
// speedup vs baseline: 1.1107x; 1.1107x over previous
#include <cuda_runtime.h>

#define E 64
#define H 8
#define HE 512
#define MAX_TOKENS 16384

typedef unsigned long long ull;

__device__ __forceinline__ ull pack2(float lo, float hi) {
    ull r; asm("mov.b64 %0, {%1, %2};" : "=l"(r) : "f"(lo), "f"(hi)); return r;
}
__device__ __forceinline__ float2 unpack2(ull v) {
    float2 f; asm("mov.b64 {%0, %1}, %2;" : "=f"(f.x), "=f"(f.y) : "l"(v)); return f;
}
__device__ __forceinline__ ull ffma2(ull a, ull b, ull c) {
    ull d; asm("fma.rn.f32x2 %0, %1, %2, %3;" : "=l"(d) : "l"(a), "l"(b), "l"(c)); return d;
}

// scratch (device globals: no cudaMalloc allowed)
__device__ __align__(16) float g_q[MAX_TOKENS * HE];
__device__ __align__(16) float g_k[MAX_TOKENS * HE];
__device__ __align__(16) float g_v[MAX_TOKENS * HE];
__device__ __align__(16) float g_res[MAX_TOKENS * HE];

// ---------------------------------------------------------------------------
// Fused QKV GEMM (round-7 config — best measured: 75.0us).
// BM=128, BN=128, K=64 staged once. 256 threads, 2 CTAs/SM.
// Warp covers 8 m-groups x 4 n-groups; A half-interleaved (1 wf / LDS.128).
// grid: (12, tokens/128); widx = blockIdx.x>>2, n-block = blockIdx.x&3.
// ---------------------------------------------------------------------------
__global__ void __launch_bounds__(256, 2)
qkv_gemm(const float* __restrict__ x,
         const float* __restrict__ Wq, const float* __restrict__ bq,
         const float* __restrict__ Wk, const float* __restrict__ bk,
         const float* __restrict__ Wv, const float* __restrict__ bv)
{
    extern __shared__ __align__(16) float smem[];
    float (*As)[2][68] = (float (*)[2][68])smem;               // [64][2][68]
    float (*Bs)[132]   = (float (*)[132])(smem + 64 * 2 * 68); // [64][132]

    const int t    = threadIdx.x;
    const int lane = t & 31;
    const int w    = t >> 5;
    const int m0   = blockIdx.y * 128;
    const int nblk = blockIdx.x;           // 0..11
    const int widx = nblk >> 2;
    const int n0   = (nblk & 3) * 128;

    const float* W    = (widx == 0) ? Wq : (widx == 1) ? Wk : Wv;
    const float* bias = (widx == 0) ? bq : (widx == 1) ? bk : bv;
    float* O          = (widx == 0) ? g_q : (widx == 1) ? g_k : g_v;

    const int G  = (w & 1) * 8 + (lane >> 2);        // m-group 0..15
    const int my = G * 8;                            // 8 m rows
    const int nx = (w >> 1) * 32 + (lane & 3) * 8;   // 8 n cols

    const int lrow = t >> 1, lseg = t & 1;
    const int sg = lrow >> 3, ssub = (lrow >> 2) & 1, spos = lrow & 3;

    // stage full K=64 tiles
#pragma unroll
    for (int half = 0; half < 2; ++half) {
        const float4* srcA = (const float4*)(x + (size_t)(m0 + lrow) * E + half * 32 + lseg * 16);
        const float4* srcB = (const float4*)(W + (size_t)(n0 + lrow) * E + half * 32 + lseg * 16);
#pragma unroll
        for (int i = 0; i < 4; ++i) {
            float4 va = srcA[i];
            float4 vb = srcB[i];
            int k = half * 32 + lseg * 16 + i * 4;
            As[k + 0][ssub][sg * 4 + spos] = va.x;
            As[k + 1][ssub][sg * 4 + spos] = va.y;
            As[k + 2][ssub][sg * 4 + spos] = va.z;
            As[k + 3][ssub][sg * 4 + spos] = va.w;
            Bs[k + 0][lrow] = vb.x; Bs[k + 1][lrow] = vb.y;
            Bs[k + 2][lrow] = vb.z; Bs[k + 3][lrow] = vb.w;
        }
    }
    __syncthreads();

    ull acc[4][8];
#pragma unroll
    for (int p = 0; p < 4; ++p)
#pragma unroll
        for (int j = 0; j < 8; ++j) acc[p][j] = 0ull;

#pragma unroll 8
    for (int k = 0; k < 64; ++k) {
        ulonglong2 qa0 = *(const ulonglong2*)&As[k][0][G * 4];  // m+0..3
        ulonglong2 qa1 = *(const ulonglong2*)&As[k][1][G * 4];  // m+4..7
        ull a[4] = { qa0.x, qa0.y, qa1.x, qa1.y };
        float bf[8];
        *(float4*)&bf[0] = *(const float4*)&Bs[k][nx];
        *(float4*)&bf[4] = *(const float4*)&Bs[k][nx + 4];
#pragma unroll
        for (int j = 0; j < 8; ++j) {
            ull b2 = pack2(bf[j], bf[j]);
#pragma unroll
            for (int p = 0; p < 4; ++p)
                acc[p][j] = ffma2(a[p], b2, acc[p][j]);
        }
    }

    float bvv[8];
#pragma unroll
    for (int j = 0; j < 8; ++j) bvv[j] = bias[n0 + nx + j];
#pragma unroll
    for (int p = 0; p < 4; ++p) {
        float2 c[8];
#pragma unroll
        for (int j = 0; j < 8; ++j) c[j] = unpack2(acc[p][j]);
        float4 o0a = { c[0].x + bvv[0], c[1].x + bvv[1], c[2].x + bvv[2], c[3].x + bvv[3] };
        float4 o0b = { c[4].x + bvv[4], c[5].x + bvv[5], c[6].x + bvv[6], c[7].x + bvv[7] };
        float4 o1a = { c[0].y + bvv[0], c[1].y + bvv[1], c[2].y + bvv[2], c[3].y + bvv[3] };
        float4 o1b = { c[4].y + bvv[4], c[5].y + bvv[5], c[6].y + bvv[6], c[7].y + bvv[7] };
        float* r0 = O + (size_t)(m0 + my + 2 * p)     * HE + n0 + nx;
        float* r1 = O + (size_t)(m0 + my + 2 * p + 1) * HE + n0 + nx;
        *(float4*)(r0)     = o0a; *(float4*)(r0 + 4) = o0b;
        *(float4*)(r1)     = o1a; *(float4*)(r1 + 4) = o1b;
    }
}

// ---------------------------------------------------------------------------
// Output GEMM: out[m][n] = sum_k g_res[m][k] * Wu[n][k] + bu[n]
// BM=128, BN=64, BK=64, 256 threads, warp = 8 m-groups x 4 n-groups.
// ---------------------------------------------------------------------------
__global__ void __launch_bounds__(256, 3)
out_gemm(const float* __restrict__ Wu, const float* __restrict__ bu,
         float* __restrict__ out)
{
    extern __shared__ __align__(16) float smem[];
    float (*As)[2][68] = (float (*)[2][68])smem;               // [64][2][68]
    float (*Bs)[68]    = (float (*)[68])(smem + 64 * 2 * 68);  // [64][68]

    const int t    = threadIdx.x;
    const int lane = t & 31;
    const int w    = t >> 5;
    const int m0   = blockIdx.x * 128;

    const int G  = (w & 1) * 8 + (lane >> 2);        // m-group 0..15
    const int my = G * 8;
    const int nx = (w >> 1) * 16 + (lane & 3) * 4;   // 4 n cols

    ull acc[4][4];
#pragma unroll
    for (int p = 0; p < 4; ++p)
#pragma unroll
        for (int j = 0; j < 4; ++j) acc[p][j] = 0ull;

    const int arow = t >> 1, aseg = t & 1;
    const int sg = arow >> 3, ssub = (arow >> 2) & 1, spos = arow & 3;
    const int brow = t >> 2, bseg = t & 3;

    for (int kc = 0; kc < HE; kc += 64) {
        __syncthreads();
        {   // A tile: 128 rows x 64 k (half-interleaved)
            const float4* src = (const float4*)(g_res + (size_t)(m0 + arow) * HE + kc + aseg * 32);
#pragma unroll
            for (int i = 0; i < 8; ++i) {
                float4 v = src[i];
                int k = aseg * 32 + i * 4;
                As[k + 0][ssub][sg * 4 + spos] = v.x;
                As[k + 1][ssub][sg * 4 + spos] = v.y;
                As[k + 2][ssub][sg * 4 + spos] = v.z;
                As[k + 3][ssub][sg * 4 + spos] = v.w;
            }
        }
        {   // B tile: 64 rows x 64 k
            const float4* src = (const float4*)(Wu + (size_t)brow * HE + kc + bseg * 16);
#pragma unroll
            for (int i = 0; i < 4; ++i) {
                float4 v = src[i];
                int k = bseg * 16 + i * 4;
                Bs[k + 0][brow] = v.x; Bs[k + 1][brow] = v.y;
                Bs[k + 2][brow] = v.z; Bs[k + 3][brow] = v.w;
            }
        }
        __syncthreads();
#pragma unroll 8
        for (int k = 0; k < 64; ++k) {
            ulonglong2 qa0 = *(const ulonglong2*)&As[k][0][G * 4];
            ulonglong2 qa1 = *(const ulonglong2*)&As[k][1][G * 4];
            ull a[4] = { qa0.x, qa0.y, qa1.x, qa1.y };
            float4 b = *(const float4*)&Bs[k][nx];
            ull b2[4] = { pack2(b.x, b.x), pack2(b.y, b.y),
                          pack2(b.z, b.z), pack2(b.w, b.w) };
#pragma unroll
            for (int j = 0; j < 4; ++j)
#pragma unroll
                for (int p = 0; p < 4; ++p)
                    acc[p][j] = ffma2(a[p], b2[j], acc[p][j]);
        }
    }

    float bvv[4];
#pragma unroll
    for (int j = 0; j < 4; ++j) bvv[j] = bu[nx + j];
#pragma unroll
    for (int p = 0; p < 4; ++p) {
        float2 c0 = unpack2(acc[p][0]);
        float2 c1 = unpack2(acc[p][1]);
        float2 c2 = unpack2(acc[p][2]);
        float2 c3 = unpack2(acc[p][3]);
        float4 o0 = { c0.x + bvv[0], c1.x + bvv[1], c2.x + bvv[2], c3.x + bvv[3] };
        float4 o1 = { c0.y + bvv[0], c1.y + bvv[1], c2.y + bvv[2], c3.y + bvv[3] };
        *(float4*)(out + (size_t)(m0 + my + 2 * p)     * E + nx) = o0;
        *(float4*)(out + (size_t)(m0 + my + 2 * p + 1) * E + nx) = o1;
    }
}

// ---------------------------------------------------------------------------
// Attention + alpha-entmax + value mix.  V2: 2 score-rows per thread.
// CTA = 256 threads = 4 tokens x 64 threads; thread (r0, half) owns rows
// {r0, r0+32}, cols [half*32, half*32+32). Each k/v LDS.128 feeds 4 FFMA2.
// ---------------------------------------------------------------------------
__global__ void __launch_bounds__(256, 2)
attn_kernel(const float* __restrict__ alpha_p)
{
    // [tl][h][g][8]: floats {cols 4g..4g+3, cols 32+4g..32+4g+3}
    __shared__ __align__(16) float ksw[4][8][8][8];
    __shared__ __align__(16) float vsw[4][8][8][8];

    const int t    = threadIdx.x;
    const int tl   = t >> 6;        // token within CTA (0..3)
    const int u    = t & 63;
    const int r0   = (u >> 1) & 31; // rows r0, r0+32
    const int half = u & 1;         // which 32 columns
    const int base = blockIdx.x * 4;
    const size_t token = (size_t)(base + tl);

    // cooperative load with half-interleaving (512 float4 per array)
#pragma unroll
    for (int it = 0; it < 2; ++it) {
        const int idx = t + it * 256;
        const float4 vk = ((const float4*)(g_k + (size_t)base * HE))[idx];
        const float4 vv = ((const float4*)(g_v + (size_t)base * HE))[idx];
        const int th = idx >> 4;    // tl*8 + h
        const int c  = idx & 15;
        const int g  = c & 7;
        const int hh = c >> 3;
        *(float4*)(&ksw[0][0][0][0] + th * 64 + g * 8 + hh * 4) = vk;
        *(float4*)(&vsw[0][0][0][0] + th * 64 + g * 8 + hh * 4) = vv;
    }

    const float alpha = *alpha_p;
    const float am1 = alpha - 1.0f;
    const float inv = 1.0f / am1;
    const float qscale = am1 * 0.125f;   // fold am1 * (1/sqrt(64)) into q

    float qa[H], qb[H];
#pragma unroll
    for (int h = 0; h < H; ++h) {
        qa[h] = g_q[token * HE + h * 64 + r0]      * qscale;
        qb[h] = g_q[token * HE + h * 64 + r0 + 32] * qscale;
    }

    __syncthreads();

    // packed score accumulation for both rows
    ull sa2[16], sb2[16];
#pragma unroll
    for (int uu = 0; uu < 16; ++uu) { sa2[uu] = 0ull; sb2[uu] = 0ull; }
#pragma unroll
    for (int h = 0; h < H; ++h) {
        const ull qha = pack2(qa[h], qa[h]);
        const ull qhb = pack2(qb[h], qb[h]);
        const ulonglong2* bp = (const ulonglong2*)&ksw[tl][h][0][0];
#pragma unroll
        for (int g = 0; g < 8; ++g) {
            ulonglong2 kk = bp[2 * g + half];
            sa2[2 * g]     = ffma2(qha, kk.x, sa2[2 * g]);
            sa2[2 * g + 1] = ffma2(qha, kk.y, sa2[2 * g + 1]);
            sb2[2 * g]     = ffma2(qhb, kk.x, sb2[2 * g]);
            sb2[2 * g + 1] = ffma2(qhb, kk.y, sb2[2 * g + 1]);
        }
    }
    float sa[32], sb[32];
#pragma unroll
    for (int uu = 0; uu < 16; ++uu) {
        float2 fa = unpack2(sa2[uu]);
        float2 fb = unpack2(sb2[uu]);
        sa[2 * uu] = fa.x; sa[2 * uu + 1] = fa.y;
        sb[2 * uu] = fb.x; sb[2 * uu + 1] = fb.y;
    }

    float mxa = sa[0], mxb = sb[0];
#pragma unroll
    for (int j = 1; j < 32; ++j) { mxa = fmaxf(mxa, sa[j]); mxb = fmaxf(mxb, sb[j]); }
    mxa = fmaxf(mxa, __shfl_xor_sync(0xffffffffu, mxa, 1));
    mxb = fmaxf(mxb, __shfl_xor_sync(0xffffffffu, mxb, 1));

    if (fabsf(inv - 2.0f) < 1e-4f) {
        // alpha = 1.5: p(z) = relu(z)^2. Newton from below + exact quadratic.
        float taua = mxa - 1.0f, taub = mxb - 1.0f;
        const float tha = mxa - 0.125f, thb = mxb - 0.125f;
#pragma unroll 1
        for (int it = 0; it < 4; ++it) {
            float S1a = 0.f, S2a = 0.f, S1b = 0.f, S2b = 0.f;
#pragma unroll
            for (int j = 0; j < 32; ++j) {
                float za = fmaxf(sa[j] - taua, 0.0f);
                float zb = fmaxf(sb[j] - taub, 0.0f);
                S1a += za; S2a = fmaf(za, za, S2a);
                S1b += zb; S2b = fmaf(zb, zb, S2b);
            }
            S1a += __shfl_xor_sync(0xffffffffu, S1a, 1);
            S2a += __shfl_xor_sync(0xffffffffu, S2a, 1);
            S1b += __shfl_xor_sync(0xffffffffu, S1b, 1);
            S2b += __shfl_xor_sync(0xffffffffu, S2b, 1);
            taua = fminf(taua + __fdividef(S2a - 1.0f, 2.0f * S1a), tha);
            taub = fminf(taub + __fdividef(S2b - 1.0f, 2.0f * S1b), thb);
        }
        // exact solve per row: cnt*tau^2 - 2*S1*tau + (S2-1) = 0 on active set
        {
            float s1a = 0.f, sqa = 0.f, cna = 0.f;
            float s1b = 0.f, sqb = 0.f, cnb = 0.f;
#pragma unroll
            for (int j = 0; j < 32; ++j) {
                float za = sa[j] - taua, zb = sb[j] - taub;
                float ma = fmaxf(za, 0.0f), mb = fmaxf(zb, 0.0f);
                s1a += ma; sqa = fmaf(ma, ma, sqa); cna += (za > 0.0f) ? 1.0f : 0.0f;
                s1b += mb; sqb = fmaf(mb, mb, sqb); cnb += (zb > 0.0f) ? 1.0f : 0.0f;
            }
            s1a += __shfl_xor_sync(0xffffffffu, s1a, 1);
            sqa += __shfl_xor_sync(0xffffffffu, sqa, 1);
            cna += __shfl_xor_sync(0xffffffffu, cna, 1);
            s1b += __shfl_xor_sync(0xffffffffu, s1b, 1);
            sqb += __shfl_xor_sync(0xffffffffu, sqb, 1);
            cnb += __shfl_xor_sync(0xffffffffu, cnb, 1);
            float S1A = fmaf(taua, cna, s1a);
            float S2A = sqa + 2.0f * taua * s1a + taua * taua * cna;
            float da = fmaxf(fmaf(-cna, S2A - 1.0f, S1A * S1A), 0.0f);
            taua = __fdividef(S1A - sqrtf(da), cna);
            float S1B = fmaf(taub, cnb, s1b);
            float S2B = sqb + 2.0f * taub * s1b + taub * taub * cnb;
            float db = fmaxf(fmaf(-cnb, S2B - 1.0f, S1B * S1B), 0.0f);
            taub = __fdividef(S1B - sqrtf(db), cnb);
        }
        float suma = 0.f, sumb = 0.f;
#pragma unroll
        for (int j = 0; j < 32; ++j) {
            float ma = fmaxf(sa[j] - taua, 0.0f);
            float mb = fmaxf(sb[j] - taub, 0.0f);
            sa[j] = ma * ma; suma += sa[j];
            sb[j] = mb * mb; sumb += sb[j];
        }
        suma += __shfl_xor_sync(0xffffffffu, suma, 1);
        sumb += __shfl_xor_sync(0xffffffffu, sumb, 1);
        float rna = __fdividef(1.0f, suma);
        float rnb = __fdividef(1.0f, sumb);
#pragma unroll
        for (int j = 0; j < 32; ++j) { sa[j] *= rna; sb[j] *= rnb; }
    } else {
        // generic alpha: faithful 50-iter bisection (both rows together)
        float tla = mxa - 1.0f, tlb = mxb - 1.0f;
        float dma = (mxa - __powf(1.0f / 64.0f, am1)) - tla;
        float dmb = (mxb - __powf(1.0f / 64.0f, am1)) - tlb;
        float pa = 0.f, pb = 0.f;
#pragma unroll
        for (int j = 0; j < 32; ++j) {
            float za = sa[j] - tla, zb = sb[j] - tlb;
            if (za > 0.0f) pa += __powf(fmaxf(za, 1e-30f), inv);
            if (zb > 0.0f) pb += __powf(fmaxf(zb, 1e-30f), inv);
        }
        pa += __shfl_xor_sync(0xffffffffu, pa, 1);
        pb += __shfl_xor_sync(0xffffffffu, pb, 1);
        const float fla = pa - 1.0f, flb = pb - 1.0f;
        float tma = tla, tmb = tlb;
#pragma unroll 1
        for (int it = 0; it < 50; ++it) {
            dma *= 0.5f; dmb *= 0.5f;
            tma = tla + dma; tmb = tlb + dmb;
            float fa = 0.f, fb = 0.f;
#pragma unroll
            for (int j = 0; j < 32; ++j) {
                float za = sa[j] - tma, zb = sb[j] - tmb;
                if (za > 0.0f) fa += __powf(fmaxf(za, 1e-30f), inv);
                if (zb > 0.0f) fb += __powf(fmaxf(zb, 1e-30f), inv);
            }
            fa += __shfl_xor_sync(0xffffffffu, fa, 1);
            fb += __shfl_xor_sync(0xffffffffu, fb, 1);
            if ((fa - 1.0f) * fla >= 0.0f) tla = tma;
            if ((fb - 1.0f) * flb >= 0.0f) tlb = tmb;
        }
        float suma = 0.f, sumb = 0.f;
#pragma unroll
        for (int j = 0; j < 32; ++j) {
            float za = sa[j] - tma, zb = sb[j] - tmb;
            sa[j] = (za > 0.0f) ? __powf(fmaxf(za, 1e-30f), inv) : 0.0f;
            sb[j] = (zb > 0.0f) ? __powf(fmaxf(zb, 1e-30f), inv) : 0.0f;
            suma += sa[j]; sumb += sb[j];
        }
        suma += __shfl_xor_sync(0xffffffffu, suma, 1);
        sumb += __shfl_xor_sync(0xffffffffu, sumb, 1);
        float rna = __fdividef(1.0f, suma);
        float rnb = __fdividef(1.0f, sumb);
#pragma unroll
        for (int j = 0; j < 32; ++j) { sa[j] *= rna; sb[j] *= rnb; }
    }

    // value mix: res[h][r] = sum_j att[r][j] * v[h][j]  (both rows, v reused)
    ull aa2[16], ab2[16];
#pragma unroll
    for (int uu = 0; uu < 16; ++uu) {
        aa2[uu] = pack2(sa[2 * uu], sa[2 * uu + 1]);
        ab2[uu] = pack2(sb[2 * uu], sb[2 * uu + 1]);
    }
#pragma unroll
    for (int h = 0; h < H; ++h) {
        ull ra2 = 0ull, rb2 = 0ull;
        const ulonglong2* bp = (const ulonglong2*)&vsw[tl][h][0][0];
#pragma unroll
        for (int g = 0; g < 8; ++g) {
            ulonglong2 vv = bp[2 * g + half];
            ra2 = ffma2(aa2[2 * g],     vv.x, ra2);
            ra2 = ffma2(aa2[2 * g + 1], vv.y, ra2);
            rb2 = ffma2(ab2[2 * g],     vv.x, rb2);
            rb2 = ffma2(ab2[2 * g + 1], vv.y, rb2);
        }
        float2 fa = unpack2(ra2);
        float2 fb = unpack2(rb2);
        float ra = fa.x + fa.y;
        float rb = fb.x + fb.y;
        ra += __shfl_xor_sync(0xffffffffu, ra, 1);
        rb += __shfl_xor_sync(0xffffffffu, rb, 1);
        if (half == (h & 1)) {
            g_res[token * HE + h * 64 + r0]      = ra;
            g_res[token * HE + h * 64 + r0 + 32] = rb;
        }
    }
}

// ---------------------------------------------------------------------------
extern "C" void kernel_launch(void* const* d_in, const int* in_sizes, int n_in,
                              void* d_out, int out_size)
{
    const float* x     = (const float*)d_in[0];
    const float* alpha = (const float*)d_in[1];
    const float* Wk    = (const float*)d_in[2];
    const float* bk    = (const float*)d_in[3];
    const float* Wq    = (const float*)d_in[4];
    const float* bq    = (const float*)d_in[5];
    const float* Wv    = (const float*)d_in[6];
    const float* bv    = (const float*)d_in[7];
    const float* Wu    = (const float*)d_in[8];
    const float* bu    = (const float*)d_in[9];

    const int tokens = in_sizes[0] / E;   // 16384

    const int qkv_smem = (64 * 2 * 68 + 64 * 132) * sizeof(float);  // 68608
    const int out_smem = (64 * 2 * 68 + 64 * 68) * sizeof(float);   // 52224
    static int attr_done = 0;
    if (!attr_done) {
        cudaFuncSetAttribute(qkv_gemm, cudaFuncAttributeMaxDynamicSharedMemorySize, qkv_smem);
        cudaFuncSetAttribute(out_gemm, cudaFuncAttributeMaxDynamicSharedMemorySize, out_smem);
        attr_done = 1;
    }

    qkv_gemm<<<dim3(12, tokens / 128), 256, qkv_smem>>>(x, Wq, bq, Wk, bk, Wv, bv);
    attn_kernel<<<tokens / 4, 256>>>(alpha);
    out_gemm<<<tokens / 128, 256, out_smem>>>(Wu, bu, (float*)d_out);
}

// round 13
// speedup vs baseline: 1.1134x; 1.0025x over previous
#include <cuda_runtime.h>

#define E 64
#define H 8
#define HE 512
#define MAX_TOKENS 16384

typedef unsigned long long ull;

__device__ __forceinline__ ull pack2(float lo, float hi) {
    ull r; asm("mov.b64 %0, {%1, %2};" : "=l"(r) : "f"(lo), "f"(hi)); return r;
}
__device__ __forceinline__ float2 unpack2(ull v) {
    float2 f; asm("mov.b64 {%0, %1}, %2;" : "=f"(f.x), "=f"(f.y) : "l"(v)); return f;
}
__device__ __forceinline__ ull ffma2(ull a, ull b, ull c) {
    ull d; asm("fma.rn.f32x2 %0, %1, %2, %3;" : "=l"(d) : "l"(a), "l"(b), "l"(c)); return d;
}

// scratch (device globals: no cudaMalloc allowed)
__device__ __align__(16) float g_q[MAX_TOKENS * HE];
__device__ __align__(16) float g_k[MAX_TOKENS * HE];
__device__ __align__(16) float g_v[MAX_TOKENS * HE];
__device__ __align__(16) float g_res[MAX_TOKENS * HE];

// ---------------------------------------------------------------------------
// Fused QKV GEMM (round-7 config — best measured: 74.8us). PROTECTED.
// BM=128, BN=128, K=64 staged once. 256 threads, 2 CTAs/SM.
// ---------------------------------------------------------------------------
__global__ void __launch_bounds__(256, 2)
qkv_gemm(const float* __restrict__ x,
         const float* __restrict__ Wq, const float* __restrict__ bq,
         const float* __restrict__ Wk, const float* __restrict__ bk,
         const float* __restrict__ Wv, const float* __restrict__ bv)
{
    extern __shared__ __align__(16) float smem[];
    float (*As)[2][68] = (float (*)[2][68])smem;               // [64][2][68]
    float (*Bs)[132]   = (float (*)[132])(smem + 64 * 2 * 68); // [64][132]

    const int t    = threadIdx.x;
    const int lane = t & 31;
    const int w    = t >> 5;
    const int m0   = blockIdx.y * 128;
    const int nblk = blockIdx.x;           // 0..11
    const int widx = nblk >> 2;
    const int n0   = (nblk & 3) * 128;

    const float* W    = (widx == 0) ? Wq : (widx == 1) ? Wk : Wv;
    const float* bias = (widx == 0) ? bq : (widx == 1) ? bk : bv;
    float* O          = (widx == 0) ? g_q : (widx == 1) ? g_k : g_v;

    const int G  = (w & 1) * 8 + (lane >> 2);        // m-group 0..15
    const int my = G * 8;                            // 8 m rows
    const int nx = (w >> 1) * 32 + (lane & 3) * 8;   // 8 n cols

    const int lrow = t >> 1, lseg = t & 1;
    const int sg = lrow >> 3, ssub = (lrow >> 2) & 1, spos = lrow & 3;

    // stage full K=64 tiles
#pragma unroll
    for (int half = 0; half < 2; ++half) {
        const float4* srcA = (const float4*)(x + (size_t)(m0 + lrow) * E + half * 32 + lseg * 16);
        const float4* srcB = (const float4*)(W + (size_t)(n0 + lrow) * E + half * 32 + lseg * 16);
#pragma unroll
        for (int i = 0; i < 4; ++i) {
            float4 va = srcA[i];
            float4 vb = srcB[i];
            int k = half * 32 + lseg * 16 + i * 4;
            As[k + 0][ssub][sg * 4 + spos] = va.x;
            As[k + 1][ssub][sg * 4 + spos] = va.y;
            As[k + 2][ssub][sg * 4 + spos] = va.z;
            As[k + 3][ssub][sg * 4 + spos] = va.w;
            Bs[k + 0][lrow] = vb.x; Bs[k + 1][lrow] = vb.y;
            Bs[k + 2][lrow] = vb.z; Bs[k + 3][lrow] = vb.w;
        }
    }
    __syncthreads();

    ull acc[4][8];
#pragma unroll
    for (int p = 0; p < 4; ++p)
#pragma unroll
        for (int j = 0; j < 8; ++j) acc[p][j] = 0ull;

#pragma unroll 8
    for (int k = 0; k < 64; ++k) {
        ulonglong2 qa0 = *(const ulonglong2*)&As[k][0][G * 4];  // m+0..3
        ulonglong2 qa1 = *(const ulonglong2*)&As[k][1][G * 4];  // m+4..7
        ull a[4] = { qa0.x, qa0.y, qa1.x, qa1.y };
        float bf[8];
        *(float4*)&bf[0] = *(const float4*)&Bs[k][nx];
        *(float4*)&bf[4] = *(const float4*)&Bs[k][nx + 4];
#pragma unroll
        for (int j = 0; j < 8; ++j) {
            ull b2 = pack2(bf[j], bf[j]);
#pragma unroll
            for (int p = 0; p < 4; ++p)
                acc[p][j] = ffma2(a[p], b2, acc[p][j]);
        }
    }

    float bvv[8];
#pragma unroll
    for (int j = 0; j < 8; ++j) bvv[j] = bias[n0 + nx + j];
#pragma unroll
    for (int p = 0; p < 4; ++p) {
        float2 c[8];
#pragma unroll
        for (int j = 0; j < 8; ++j) c[j] = unpack2(acc[p][j]);
        float4 o0a = { c[0].x + bvv[0], c[1].x + bvv[1], c[2].x + bvv[2], c[3].x + bvv[3] };
        float4 o0b = { c[4].x + bvv[4], c[5].x + bvv[5], c[6].x + bvv[6], c[7].x + bvv[7] };
        float4 o1a = { c[0].y + bvv[0], c[1].y + bvv[1], c[2].y + bvv[2], c[3].y + bvv[3] };
        float4 o1b = { c[4].y + bvv[4], c[5].y + bvv[5], c[6].y + bvv[6], c[7].y + bvv[7] };
        float* r0 = O + (size_t)(m0 + my + 2 * p)     * HE + n0 + nx;
        float* r1 = O + (size_t)(m0 + my + 2 * p + 1) * HE + n0 + nx;
        *(float4*)(r0)     = o0a; *(float4*)(r0 + 4) = o0b;
        *(float4*)(r1)     = o1a; *(float4*)(r1 + 4) = o1b;
    }
}

// ---------------------------------------------------------------------------
// Output GEMM (PROTECTED): out[m][n] = sum_k g_res[m][k] * Wu[n][k] + bu[n]
// ---------------------------------------------------------------------------
__global__ void __launch_bounds__(256, 3)
out_gemm(const float* __restrict__ Wu, const float* __restrict__ bu,
         float* __restrict__ out)
{
    extern __shared__ __align__(16) float smem[];
    float (*As)[2][68] = (float (*)[2][68])smem;               // [64][2][68]
    float (*Bs)[68]    = (float (*)[68])(smem + 64 * 2 * 68);  // [64][68]

    const int t    = threadIdx.x;
    const int lane = t & 31;
    const int w    = t >> 5;
    const int m0   = blockIdx.x * 128;

    const int G  = (w & 1) * 8 + (lane >> 2);        // m-group 0..15
    const int my = G * 8;
    const int nx = (w >> 1) * 16 + (lane & 3) * 4;   // 4 n cols

    ull acc[4][4];
#pragma unroll
    for (int p = 0; p < 4; ++p)
#pragma unroll
        for (int j = 0; j < 4; ++j) acc[p][j] = 0ull;

    const int arow = t >> 1, aseg = t & 1;
    const int sg = arow >> 3, ssub = (arow >> 2) & 1, spos = arow & 3;
    const int brow = t >> 2, bseg = t & 3;

    for (int kc = 0; kc < HE; kc += 64) {
        __syncthreads();
        {   // A tile: 128 rows x 64 k (half-interleaved)
            const float4* src = (const float4*)(g_res + (size_t)(m0 + arow) * HE + kc + aseg * 32);
#pragma unroll
            for (int i = 0; i < 8; ++i) {
                float4 v = src[i];
                int k = aseg * 32 + i * 4;
                As[k + 0][ssub][sg * 4 + spos] = v.x;
                As[k + 1][ssub][sg * 4 + spos] = v.y;
                As[k + 2][ssub][sg * 4 + spos] = v.z;
                As[k + 3][ssub][sg * 4 + spos] = v.w;
            }
        }
        {   // B tile: 64 rows x 64 k
            const float4* src = (const float4*)(Wu + (size_t)brow * HE + kc + bseg * 16);
#pragma unroll
            for (int i = 0; i < 4; ++i) {
                float4 v = src[i];
                int k = bseg * 16 + i * 4;
                Bs[k + 0][brow] = v.x; Bs[k + 1][brow] = v.y;
                Bs[k + 2][brow] = v.z; Bs[k + 3][brow] = v.w;
            }
        }
        __syncthreads();
#pragma unroll 8
        for (int k = 0; k < 64; ++k) {
            ulonglong2 qa0 = *(const ulonglong2*)&As[k][0][G * 4];
            ulonglong2 qa1 = *(const ulonglong2*)&As[k][1][G * 4];
            ull a[4] = { qa0.x, qa0.y, qa1.x, qa1.y };
            float4 b = *(const float4*)&Bs[k][nx];
            ull b2[4] = { pack2(b.x, b.x), pack2(b.y, b.y),
                          pack2(b.z, b.z), pack2(b.w, b.w) };
#pragma unroll
            for (int j = 0; j < 4; ++j)
#pragma unroll
                for (int p = 0; p < 4; ++p)
                    acc[p][j] = ffma2(a[p], b2[j], acc[p][j]);
        }
    }

    float bvv[4];
#pragma unroll
    for (int j = 0; j < 4; ++j) bvv[j] = bu[nx + j];
#pragma unroll
    for (int p = 0; p < 4; ++p) {
        float2 c0 = unpack2(acc[p][0]);
        float2 c1 = unpack2(acc[p][1]);
        float2 c2 = unpack2(acc[p][2]);
        float2 c3 = unpack2(acc[p][3]);
        float4 o0 = { c0.x + bvv[0], c1.x + bvv[1], c2.x + bvv[2], c3.x + bvv[3] };
        float4 o1 = { c0.y + bvv[0], c1.y + bvv[1], c2.y + bvv[2], c3.y + bvv[3] };
        *(float4*)(out + (size_t)(m0 + my + 2 * p)     * E + nx) = o0;
        *(float4*)(out + (size_t)(m0 + my + 2 * p + 1) * E + nx) = o1;
    }
}

// ---------------------------------------------------------------------------
// Attention + alpha-entmax + value mix.  V4: 2 rows/thread,
// Newton 4 (proven) + exact quadratic, normalization folded into output.
// ---------------------------------------------------------------------------
__global__ void __launch_bounds__(256, 2)
attn_kernel(const float* __restrict__ alpha_p)
{
    // [tl][h][g][8]: floats {cols 4g..4g+3, cols 32+4g..32+4g+3}
    __shared__ __align__(16) float ksw[4][8][8][8];
    __shared__ __align__(16) float vsw[4][8][8][8];

    const int t    = threadIdx.x;
    const int tl   = t >> 6;        // token within CTA (0..3)
    const int u    = t & 63;
    const int r0   = (u >> 1) & 31; // rows r0, r0+32
    const int half = u & 1;         // which 32 columns
    const int base = blockIdx.x * 4;
    const size_t token = (size_t)(base + tl);

    // cooperative load with half-interleaving (512 float4 per array)
#pragma unroll
    for (int it = 0; it < 2; ++it) {
        const int idx = t + it * 256;
        const float4 vk = ((const float4*)(g_k + (size_t)base * HE))[idx];
        const float4 vv = ((const float4*)(g_v + (size_t)base * HE))[idx];
        const int th = idx >> 4;    // tl*8 + h
        const int c  = idx & 15;
        const int g  = c & 7;
        const int hh = c >> 3;
        *(float4*)(&ksw[0][0][0][0] + th * 64 + g * 8 + hh * 4) = vk;
        *(float4*)(&vsw[0][0][0][0] + th * 64 + g * 8 + hh * 4) = vv;
    }

    const float alpha = *alpha_p;
    const float am1 = alpha - 1.0f;
    const float inv = 1.0f / am1;
    const float qscale = am1 * 0.125f;   // fold am1 * (1/sqrt(64)) into q

    float qa[H], qb[H];
#pragma unroll
    for (int h = 0; h < H; ++h) {
        qa[h] = g_q[token * HE + h * 64 + r0]      * qscale;
        qb[h] = g_q[token * HE + h * 64 + r0 + 32] * qscale;
    }

    __syncthreads();

    // packed score accumulation for both rows
    ull sa2[16], sb2[16];
#pragma unroll
    for (int uu = 0; uu < 16; ++uu) { sa2[uu] = 0ull; sb2[uu] = 0ull; }
#pragma unroll
    for (int h = 0; h < H; ++h) {
        const ull qha = pack2(qa[h], qa[h]);
        const ull qhb = pack2(qb[h], qb[h]);
        const ulonglong2* bp = (const ulonglong2*)&ksw[tl][h][0][0];
#pragma unroll
        for (int g = 0; g < 8; ++g) {
            ulonglong2 kk = bp[2 * g + half];
            sa2[2 * g]     = ffma2(qha, kk.x, sa2[2 * g]);
            sa2[2 * g + 1] = ffma2(qha, kk.y, sa2[2 * g + 1]);
            sb2[2 * g]     = ffma2(qhb, kk.x, sb2[2 * g]);
            sb2[2 * g + 1] = ffma2(qhb, kk.y, sb2[2 * g + 1]);
        }
    }
    float sa[32], sb[32];
#pragma unroll
    for (int uu = 0; uu < 16; ++uu) {
        float2 fa = unpack2(sa2[uu]);
        float2 fb = unpack2(sb2[uu]);
        sa[2 * uu] = fa.x; sa[2 * uu + 1] = fa.y;
        sb[2 * uu] = fb.x; sb[2 * uu + 1] = fb.y;
    }

    float mxa = sa[0], mxb = sb[0];
#pragma unroll
    for (int j = 1; j < 32; ++j) { mxa = fmaxf(mxa, sa[j]); mxb = fmaxf(mxb, sb[j]); }
    mxa = fmaxf(mxa, __shfl_xor_sync(0xffffffffu, mxa, 1));
    mxb = fmaxf(mxb, __shfl_xor_sync(0xffffffffu, mxb, 1));

    float rna, rnb;   // normalization (applied at output)

    if (fabsf(inv - 2.0f) < 1e-4f) {
        // alpha = 1.5: p(z) = relu(z)^2. 4 Newton (from below) + exact quadratic.
        float taua = mxa - 1.0f, taub = mxb - 1.0f;
        const float tha = mxa - 0.125f, thb = mxb - 0.125f;
#pragma unroll 1
        for (int it = 0; it < 4; ++it) {
            float S1a = 0.f, S2a = 0.f, S1b = 0.f, S2b = 0.f;
#pragma unroll
            for (int j = 0; j < 32; ++j) {
                float za = fmaxf(sa[j] - taua, 0.0f);
                float zb = fmaxf(sb[j] - taub, 0.0f);
                S1a += za; S2a = fmaf(za, za, S2a);
                S1b += zb; S2b = fmaf(zb, zb, S2b);
            }
            S1a += __shfl_xor_sync(0xffffffffu, S1a, 1);
            S2a += __shfl_xor_sync(0xffffffffu, S2a, 1);
            S1b += __shfl_xor_sync(0xffffffffu, S1b, 1);
            S2b += __shfl_xor_sync(0xffffffffu, S2b, 1);
            taua = fminf(taua + __fdividef(S2a - 1.0f, 2.0f * S1a), tha);
            taub = fminf(taub + __fdividef(S2b - 1.0f, 2.0f * S1b), thb);
        }
        // exact solve per row: cnt*tau^2 - 2*S1*tau + (S2-1) = 0 on active set
        {
            float s1a = 0.f, sqa = 0.f, cna = 0.f;
            float s1b = 0.f, sqb = 0.f, cnb = 0.f;
#pragma unroll
            for (int j = 0; j < 32; ++j) {
                float za = sa[j] - taua, zb = sb[j] - taub;
                float ma = fmaxf(za, 0.0f), mb = fmaxf(zb, 0.0f);
                s1a += ma; sqa = fmaf(ma, ma, sqa); cna += (za > 0.0f) ? 1.0f : 0.0f;
                s1b += mb; sqb = fmaf(mb, mb, sqb); cnb += (zb > 0.0f) ? 1.0f : 0.0f;
            }
            s1a += __shfl_xor_sync(0xffffffffu, s1a, 1);
            sqa += __shfl_xor_sync(0xffffffffu, sqa, 1);
            cna += __shfl_xor_sync(0xffffffffu, cna, 1);
            s1b += __shfl_xor_sync(0xffffffffu, s1b, 1);
            sqb += __shfl_xor_sync(0xffffffffu, sqb, 1);
            cnb += __shfl_xor_sync(0xffffffffu, cnb, 1);
            float S1A = fmaf(taua, cna, s1a);
            float S2A = sqa + 2.0f * taua * s1a + taua * taua * cna;
            float da = fmaxf(fmaf(-cna, S2A - 1.0f, S1A * S1A), 0.0f);
            taua = __fdividef(S1A - sqrtf(da), cna);
            float S1B = fmaf(taub, cnb, s1b);
            float S2B = sqb + 2.0f * taub * s1b + taub * taub * cnb;
            float db = fmaxf(fmaf(-cnb, S2B - 1.0f, S1B * S1B), 0.0f);
            taub = __fdividef(S1B - sqrtf(db), cnb);
        }
        float suma = 0.f, sumb = 0.f;
#pragma unroll
        for (int j = 0; j < 32; ++j) {
            float ma = fmaxf(sa[j] - taua, 0.0f);
            float mb = fmaxf(sb[j] - taub, 0.0f);
            sa[j] = ma * ma; suma += sa[j];
            sb[j] = mb * mb; sumb += sb[j];
        }
        suma += __shfl_xor_sync(0xffffffffu, suma, 1);
        sumb += __shfl_xor_sync(0xffffffffu, sumb, 1);
        rna = __fdividef(1.0f, suma);
        rnb = __fdividef(1.0f, sumb);
    } else {
        // generic alpha: faithful 50-iter bisection (both rows together)
        float tla = mxa - 1.0f, tlb = mxb - 1.0f;
        float dma = (mxa - __powf(1.0f / 64.0f, am1)) - tla;
        float dmb = (mxb - __powf(1.0f / 64.0f, am1)) - tlb;
        float pa = 0.f, pb = 0.f;
#pragma unroll
        for (int j = 0; j < 32; ++j) {
            float za = sa[j] - tla, zb = sb[j] - tlb;
            if (za > 0.0f) pa += __powf(fmaxf(za, 1e-30f), inv);
            if (zb > 0.0f) pb += __powf(fmaxf(zb, 1e-30f), inv);
        }
        pa += __shfl_xor_sync(0xffffffffu, pa, 1);
        pb += __shfl_xor_sync(0xffffffffu, pb, 1);
        const float fla = pa - 1.0f, flb = pb - 1.0f;
        float tma = tla, tmb = tlb;
#pragma unroll 1
        for (int it = 0; it < 50; ++it) {
            dma *= 0.5f; dmb *= 0.5f;
            tma = tla + dma; tmb = tlb + dmb;
            float fa = 0.f, fb = 0.f;
#pragma unroll
            for (int j = 0; j < 32; ++j) {
                float za = sa[j] - tma, zb = sb[j] - tmb;
                if (za > 0.0f) fa += __powf(fmaxf(za, 1e-30f), inv);
                if (zb > 0.0f) fb += __powf(fmaxf(zb, 1e-30f), inv);
            }
            fa += __shfl_xor_sync(0xffffffffu, fa, 1);
            fb += __shfl_xor_sync(0xffffffffu, fb, 1);
            if ((fa - 1.0f) * fla >= 0.0f) tla = tma;
            if ((fb - 1.0f) * flb >= 0.0f) tlb = tmb;
        }
        float suma = 0.f, sumb = 0.f;
#pragma unroll
        for (int j = 0; j < 32; ++j) {
            float za = sa[j] - tma, zb = sb[j] - tmb;
            sa[j] = (za > 0.0f) ? __powf(fmaxf(za, 1e-30f), inv) : 0.0f;
            sb[j] = (zb > 0.0f) ? __powf(fmaxf(zb, 1e-30f), inv) : 0.0f;
            suma += sa[j]; sumb += sb[j];
        }
        suma += __shfl_xor_sync(0xffffffffu, suma, 1);
        sumb += __shfl_xor_sync(0xffffffffu, sumb, 1);
        rna = __fdividef(1.0f, suma);
        rnb = __fdividef(1.0f, sumb);
    }

    // value mix: res[h][r] = (sum_j att[r][j] * v[h][j]) * rn  (norm folded)
    ull aa2[16], ab2[16];
#pragma unroll
    for (int uu = 0; uu < 16; ++uu) {
        aa2[uu] = pack2(sa[2 * uu], sa[2 * uu + 1]);
        ab2[uu] = pack2(sb[2 * uu], sb[2 * uu + 1]);
    }
#pragma unroll
    for (int h = 0; h < H; ++h) {
        ull ra2 = 0ull, rb2 = 0ull;
        const ulonglong2* bp = (const ulonglong2*)&vsw[tl][h][0][0];
#pragma unroll
        for (int g = 0; g < 8; ++g) {
            ulonglong2 vv = bp[2 * g + half];
            ra2 = ffma2(aa2[2 * g],     vv.x, ra2);
            ra2 = ffma2(aa2[2 * g + 1], vv.y, ra2);
            rb2 = ffma2(ab2[2 * g],     vv.x, rb2);
            rb2 = ffma2(ab2[2 * g + 1], vv.y, rb2);
        }
        float2 fa = unpack2(ra2);
        float2 fb = unpack2(rb2);
        float ra = fa.x + fa.y;
        float rb = fb.x + fb.y;
        ra += __shfl_xor_sync(0xffffffffu, ra, 1);
        rb += __shfl_xor_sync(0xffffffffu, rb, 1);
        if (half == (h & 1)) {
            g_res[token * HE + h * 64 + r0]      = ra * rna;
            g_res[token * HE + h * 64 + r0 + 32] = rb * rnb;
        }
    }
}

// ---------------------------------------------------------------------------
extern "C" void kernel_launch(void* const* d_in, const int* in_sizes, int n_in,
                              void* d_out, int out_size)
{
    const float* x     = (const float*)d_in[0];
    const float* alpha = (const float*)d_in[1];
    const float* Wk    = (const float*)d_in[2];
    const float* bk    = (const float*)d_in[3];
    const float* Wq    = (const float*)d_in[4];
    const float* bq    = (const float*)d_in[5];
    const float* Wv    = (const float*)d_in[6];
    const float* bv    = (const float*)d_in[7];
    const float* Wu    = (const float*)d_in[8];
    const float* bu    = (const float*)d_in[9];

    const int tokens = in_sizes[0] / E;   // 16384

    const int qkv_smem = (64 * 2 * 68 + 64 * 132) * sizeof(float);  // 68608
    const int out_smem = (64 * 2 * 68 + 64 * 68) * sizeof(float);   // 52224
    static int attr_done = 0;
    if (!attr_done) {
        cudaFuncSetAttribute(qkv_gemm, cudaFuncAttributeMaxDynamicSharedMemorySize, qkv_smem);
        cudaFuncSetAttribute(out_gemm, cudaFuncAttributeMaxDynamicSharedMemorySize, out_smem);
        attr_done = 1;
    }

    qkv_gemm<<<dim3(12, tokens / 128), 256, qkv_smem>>>(x, Wq, bq, Wk, bk, Wv, bv);
    attn_kernel<<<tokens / 4, 256>>>(alpha);
    out_gemm<<<tokens / 128, 256, out_smem>>>(Wu, bu, (float*)d_out);
}